// round 6
// baseline (speedup 1.0000x reference)
#include <cuda_runtime.h>
#include <math.h>

#define NN 10000
#define NSLICE 14
#define NCHUNK 10
#define NB 140                 // all co-resident (<=148 SMs)
#define NT 512
#define OUTB 1024              // outputs per chunk (2 per thread)
#define MAXR 110               // max table rows any block needs
#define TW2 200                // u16 row width (even)
#define AWORDS (MAXR * 100)    // u32 words per table copy = 11000
#define DB (AWORDS * 4)        // byte offset of copy B = 44000
#define SLIST_OFF (2 * DB)     // 88000, 16B aligned
#define SLIST_MAX 720
#define SMEM_BYTES (SLIST_OFF + SLIST_MAX * 4)
#define NSEG 313
#define CPB 100                // compaction block (no A-row duty)
#define QSCALE 448.0f

__device__ float g_A[NN];                // A[di*100+j1] = sum_j2 sqrt(di^2+(j1-j2)^2)
__device__ int   g_list[NN];             // (i2+99)*200 + (j2+99)
__device__ int   g_nlist;
__device__ float g_pT[NSLICE * 10240];
__device__ float g_pS[NSLICE * 10240];
__device__ float g_red[NCHUNK];
__device__ int   g_barA = 0, g_barB = 0, g_ctr2 = 0, g_done = 0;

__device__ __forceinline__ void grid_barrier(int* ctr) {
    __syncthreads();
    if (threadIdx.x == 0) {
        atomicAdd(ctr, 1);
        while (*(volatile int*)ctr != NB) __nanosleep(32);
    }
    __syncthreads();
}

__device__ __forceinline__ float sqrt_fast(float x) {
    float r; asm("sqrt.approx.f32 %0, %1;" : "=f"(r) : "f"(x)); return r;
}

__global__ __launch_bounds__(NT, 1) void k_fused(const float* __restrict__ prob,
                                                 const float* __restrict__ gt,
                                                 float* __restrict__ out) {
    extern __shared__ unsigned char smraw[];
    unsigned* wA = (unsigned*)smraw;                 // u16-pair words, copy A
    unsigned* wB = (unsigned*)(smraw + DB);          // shifted copy B
    int* slist = (int*)(smraw + SLIST_OFF);

    const int bid = blockIdx.x;
    const int tid = threadIdx.x;
    const int warp = tid >> 5, lane = tid & 31;

    const int chunk = bid / NSLICE;
    const int s = bid - chunk * NSLICE;
    const int o0 = chunk * OUTB;
    const int i1lo = o0 / 100;
    int i1hi = (o0 + OUTB - 1) / 100; if (i1hi > 99) i1hi = 99;
    const int rlo = 99 - i1hi;
    const int nrows = 100 + (i1hi - i1lo);
    const int nW = nrows * 100;                      // u32 words per copy

    // ---------------- Phase A ----------------
    // Compaction block: issue ALL 20 gt loads up front (MLP=20, one DRAM/L2
    // round trip) so the latency hides under the table fill below. The
    // ballots run after the fill with data already in registers.
    float v[20];
    if (bid == CPB) {
        #pragma unroll
        for (int it = 0; it < 20; ++it) {
            int seg = it * 16 + warp;
            int o = seg * 32 + lane;
            v[it] = (o < NN) ? gt[o] : 0.0f;
        }
    } else if (bid < 100) {
        // one A-row per block (full fp32 precision)
        int j1 = tid;
        if (j1 < 100) {
            float fd2 = (float)(bid * bid);
            float a = 0.f;
            #pragma unroll 4
            for (int j2 = 0; j2 < 100; ++j2) {
                float dj = (float)(j1 - j2);
                a += sqrtf(fd2 + dj * dj);
            }
            g_A[bid * 100 + j1] = a;
        }
    }

    // all blocks: copy A of quantized table (u16 pairs)
    for (int w = tid; w < nW; w += NT) {
        int r = w / 100;
        int cw = w - r * 100;
        int dx = r + rlo - 99;
        int c0 = 2 * cw - 99;            // dy of even col
        int d2a = dx * dx + c0 * c0;
        int d2b = dx * dx + (c0 + 1) * (c0 + 1);
        unsigned ua = __float2uint_rn(sqrt_fast((float)d2a) * QSCALE);
        unsigned ub = __float2uint_rn(sqrt_fast((float)d2b) * QSCALE);
        wA[w] = ua | (ub << 16);
    }
    __syncthreads();
    // copy B: B[k] = A[k+1]  (one-u16 shift, built from copy A)
    for (int w = tid; w < nW; w += NT) {
        unsigned a = wA[w];
        unsigned b = wA[(w + 1 < nW) ? (w + 1) : w];
        wB[w] = __byte_perm(a, b, 0x5432);
    }

    if (bid == CPB) {
        // deterministic parallel compaction of py = (gt >= 0.5), data in regs
        __shared__ unsigned sbal[320];
        __shared__ int soff[320];
        #pragma unroll
        for (int it = 0; it < 20; ++it) {
            int seg = it * 16 + warp;
            if (seg < NSEG) {
                int o = seg * 32 + lane;
                bool p = (o < NN) && (v[it] >= 0.5f);
                unsigned bal = __ballot_sync(0xffffffffu, p);
                if (lane == 0) sbal[seg] = bal;
            }
        }
        __syncthreads();
        if (warp == 0) {
            int base = 0;
            #pragma unroll
            for (int c = 0; c < 10; ++c) {
                int sg = c * 32 + lane;
                int cnt = (sg < NSEG) ? __popc(sbal[sg]) : 0;
                int incl = cnt;
                #pragma unroll
                for (int d = 1; d < 32; d <<= 1) {
                    int vv = __shfl_up_sync(0xffffffffu, incl, d);
                    if (lane >= d) incl += vv;
                }
                if (sg < NSEG) soff[sg] = base + incl - cnt;
                base += __shfl_sync(0xffffffffu, incl, 31);
            }
            if (lane == 0) g_nlist = base;
        }
        __syncthreads();
        #pragma unroll
        for (int it = 0; it < 20; ++it) {
            int seg = it * 16 + warp;
            if (seg < NSEG) {
                unsigned bal = sbal[seg];
                if ((bal >> lane) & 1u) {
                    int o = seg * 32 + lane;
                    int pre = __popc(bal & ((1u << lane) - 1u));
                    int i2 = o / 100, j2 = o - i2 * 100;
                    g_list[soff[seg] + pre] = (i2 + 99) * TW2 + (j2 + 99);
                }
            }
        }
    }

    __threadfence();
    grid_barrier(&g_barA);

    // ---------------- Phase B: main sparse accumulate ----------------
    int n = *(volatile int*)&g_nlist;
    int e0 = (s * n) / NSLICE;
    int e1 = ((s + 1) * n) / NSLICE;
    int cnt = e1 - e0;
    int badj = rlo * TW2 + 1;            // F = G - badj
    for (int k = tid; k < cnt; k += NT) {
        int F = g_list[e0 + k] - badj;
        int p = F & 1;
        slist[k] = 2 * (F - p) + p * DB;
    }
    __syncthreads();

    int oe = o0 + 2 * tid;               // even output; pair (oe, oe+1)
    bool valid = (oe < NN);
    int oc = valid ? oe : (NN - 2);
    int i1 = oc / 100;
    int j1 = oc - i1 * 100;              // even
    int qq = j1 >> 1;

    unsigned baseA;
    asm("{ .reg .u64 t; cvta.to.shared.u64 t, %1; cvt.u32.u64 %0, t; }"
        : "=r"(baseA) : "l"(smraw));
    unsigned tb = baseA - 400u * (unsigned)i1 - 4u * (unsigned)qq;

    unsigned aE0 = 0, aE1 = 0, aO0 = 0, aO1 = 0;
    int k = 0;
    int n8 = cnt & ~7;
    for (; k < n8; k += 8) {
        int4 ea = *(const int4*)(slist + k);
        int4 eb = *(const int4*)(slist + k + 4);
        unsigned w0, w1, w2, w3, w4, w5, w6, w7;
        asm("ld.shared.u32 %0,[%1];" : "=r"(w0) : "r"(tb + (unsigned)ea.x));
        asm("ld.shared.u32 %0,[%1];" : "=r"(w1) : "r"(tb + (unsigned)ea.y));
        asm("ld.shared.u32 %0,[%1];" : "=r"(w2) : "r"(tb + (unsigned)ea.z));
        asm("ld.shared.u32 %0,[%1];" : "=r"(w3) : "r"(tb + (unsigned)ea.w));
        asm("ld.shared.u32 %0,[%1];" : "=r"(w4) : "r"(tb + (unsigned)eb.x));
        asm("ld.shared.u32 %0,[%1];" : "=r"(w5) : "r"(tb + (unsigned)eb.y));
        asm("ld.shared.u32 %0,[%1];" : "=r"(w6) : "r"(tb + (unsigned)eb.z));
        asm("ld.shared.u32 %0,[%1];" : "=r"(w7) : "r"(tb + (unsigned)eb.w));
        aE0 = __dp2a_lo(w0, 0x0100u, aE0); aO0 = __dp2a_lo(w0, 0x0001u, aO0);
        aE1 = __dp2a_lo(w1, 0x0100u, aE1); aO1 = __dp2a_lo(w1, 0x0001u, aO1);
        aE0 = __dp2a_lo(w2, 0x0100u, aE0); aO0 = __dp2a_lo(w2, 0x0001u, aO0);
        aE1 = __dp2a_lo(w3, 0x0100u, aE1); aO1 = __dp2a_lo(w3, 0x0001u, aO1);
        aE0 = __dp2a_lo(w4, 0x0100u, aE0); aO0 = __dp2a_lo(w4, 0x0001u, aO0);
        aE1 = __dp2a_lo(w5, 0x0100u, aE1); aO1 = __dp2a_lo(w5, 0x0001u, aO1);
        aE0 = __dp2a_lo(w6, 0x0100u, aE0); aO0 = __dp2a_lo(w6, 0x0001u, aO0);
        aE1 = __dp2a_lo(w7, 0x0100u, aE1); aO1 = __dp2a_lo(w7, 0x0001u, aO1);
    }
    for (; k < cnt; ++k) {
        unsigned w0;
        asm("ld.shared.u32 %0,[%1];" : "=r"(w0) : "r"(tb + (unsigned)slist[k]));
        aE0 = __dp2a_lo(w0, 0x0100u, aE0);
        aO0 = __dp2a_lo(w0, 0x0001u, aO0);
    }
    float Te = __uint2float_rn(aE0 + aE1) * (1.0f / QSCALE);
    float To = __uint2float_rn(aO0 + aO1) * (1.0f / QSCALE);

    // slice partial of the (input-independent) rowsum S for both outputs
    int i2a = (100 * s) / NSLICE;
    int i2b = (100 * (s + 1)) / NSLICE;
    float sve = 0.f, svo = 0.f;
    const float2* A2 = (const float2*)g_A;
    for (int i2 = i2a; i2 < i2b; ++i2) {
        int di = i1 - i2; if (di < 0) di = -di;
        float2 vv = A2[di * 50 + qq];
        sve += vv.x; svo += vv.y;
    }

    if (valid) {
        *(float2*)&g_pT[s * 10240 + oe] = make_float2(Te, To);
        *(float2*)&g_pS[s * 10240 + oe] = make_float2(sve, svo);
    }
    __threadfence();
    grid_barrier(&g_barB);

    // ---------------- Phase C: reduce (blocks with s == 0) ----------------
    if (s == 0) {
        __shared__ float warpsum[16];
        float ls = 0.f;
        if (valid) {
            float Txe = 0.f, Txo = 0.f, Sxe = 0.f, Sxo = 0.f;
            int widx = (o0 >> 1) + tid;
            #pragma unroll
            for (int q2 = 0; q2 < NSLICE; ++q2) {
                float2 t2 = ((const float2*)(g_pT + q2 * 10240))[widx];
                float2 s2 = ((const float2*)(g_pS + q2 * 10240))[widx];
                Txe += t2.x; Txo += t2.y;
                Sxe += s2.x; Sxo += s2.y;
            }
            float2 pr = *(const float2*)&prob[oe];
            float pxe = (pr.x >= 0.5f) ? 1.0f : 0.0f;
            float pxo = (pr.y >= 0.5f) ? 1.0f : 0.0f;
            ls = fabsf(pxe * Sxe - Txe) + fabsf(pxo * Sxo - Txo);
        }
        #pragma unroll
        for (int off = 16; off; off >>= 1) ls += __shfl_down_sync(0xffffffffu, ls, off);
        if (lane == 0) warpsum[warp] = ls;
        __syncthreads();
        if (tid == 0) {
            float t = 0.f;
            #pragma unroll
            for (int w = 0; w < 16; ++w) t += warpsum[w];
            g_red[chunk] = t;
            __threadfence();
            int old = atomicAdd(&g_ctr2, 1);
            if (old == NCHUNK - 1) {
                float tt = 0.f;
                #pragma unroll
                for (int b = 0; b < NCHUNK; ++b) tt += g_red[b];
                out[0] = tt * (1.0f / ((float)NN * (float)NN));
            }
        }
        __syncthreads();
    }

    // ---------------- replay-safe counter reset ----------------
    __syncthreads();
    if (tid == 0) {
        int fin = atomicAdd(&g_done, 1);
        if (fin == NB - 1) {
            g_barA = 0; g_barB = 0; g_ctr2 = 0; g_done = 0;
            __threadfence();
        }
    }
}

extern "C" void kernel_launch(void* const* d_in, const int* in_sizes, int n_in,
                              void* d_out, int out_size) {
    const float* prob = (const float*)d_in[0];
    const float* gt   = (const float*)d_in[1];
    float* out = (float*)d_out;

    cudaFuncSetAttribute(k_fused, cudaFuncAttributeMaxDynamicSharedMemorySize, SMEM_BYTES);
    k_fused<<<NB, NT, SMEM_BYTES>>>(prob, gt, out);
}